// round 12
// baseline (speedup 1.0000x reference)
#include <cuda_runtime.h>
#include <cuda_fp16.h>
#include <math.h>

#define N_NODES 50000
#define FIN 128
#define H1 8
#define F1 128
#define E_MAX 800000
#define ET_MAX (E_MAX + N_NODES)
#define NEG_SLOPE 0.2f
#define SCAN_NB ((N_NODES + 1023) / 1024)   // 49

// ------------------------- scratch -------------------------
__device__ __half g_h1h[N_NODES * F1];     // fp16 x @ W1 (node1 gathers)
__device__ float g_asrc[N_NODES * H1];
__device__ float g_adst[N_NODES * H1];
__device__ float4 g_n2[N_NODES];           // packed (a2s, h2.x, h2.y, 0)
__device__ float g_a2d[N_NODES];
__device__ int   g_src[ET_MAX];
__device__ int   g_dst[ET_MAX];
__device__ int   g_csr_src[ET_MAX];
__device__ int   g_start[N_NODES + 1];
__device__ int   g_deg[N_NODES];
__device__ int   g_cnt[N_NODES];
__device__ int   g_bsum[SCAN_NB];
__device__ int   g_is64;

__device__ __forceinline__ float leaky(float v) { return v > 0.f ? v : NEG_SLOPE * v; }

// ------------------------- dtype probe + counter zero (merged) -------------------------
__global__ void probe_zero_kernel(const void* ei) {
    int i = blockIdx.x * blockDim.x + threadIdx.x;
    if (i < N_NODES) { g_deg[i] = 0; g_cnt[i] = 0; }
    if (blockIdx.x == 0) {
        const long long* p = (const long long*)ei;
        int bad = 0;
        for (int k = threadIdx.x; k < 2048; k += 256) {
            long long v = p[k];
            if (v < 0 || v >= (long long)N_NODES) bad = 1;
        }
        bad = __syncthreads_or(bad);
        if (threadIdx.x == 0) g_is64 = bad ? 0 : 1;
    }
}

__global__ void convert_kernel(const void* ei, int E, int ET) {
    int i = blockIdx.x * blockDim.x + threadIdx.x;
    if (i >= ET) return;
    int s, d;
    if (i < E) {
        if (g_is64) {
            const long long* p = (const long long*)ei;
            s = (int)p[i]; d = (int)p[E + i];
        } else {
            const int* p = (const int*)ei;
            s = p[i]; d = p[E + i];
        }
    } else {
        s = d = i - E;
    }
    g_src[i] = s;
    g_dst[i] = d;
    atomicAdd(&g_deg[d], 1);
}

// ------------------------- scan: per-block scan (A), fused block-offset add (BC) -------------------------
__global__ void scanA_kernel() {
    int i = blockIdx.x * 1024 + threadIdx.x;
    int v = (i < N_NODES) ? g_deg[i] : 0;
    int lane = threadIdx.x & 31, wid = threadIdx.x >> 5;
    int x = v;
#pragma unroll
    for (int o = 1; o < 32; o <<= 1) {
        int t = __shfl_up_sync(0xffffffffu, x, o);
        if (lane >= o) x += t;
    }
    __shared__ int wsum[32];
    if (lane == 31) wsum[wid] = x;
    __syncthreads();
    if (wid == 0) {
        int y = wsum[lane];
#pragma unroll
        for (int o = 1; o < 32; o <<= 1) {
            int t = __shfl_up_sync(0xffffffffu, y, o);
            if (lane >= o) y += t;
        }
        wsum[lane] = y;
    }
    __syncthreads();
    int incl = x + (wid > 0 ? wsum[wid - 1] : 0);
    if (i < N_NODES) g_start[i] = incl - v;
    if (threadIdx.x == 1023) g_bsum[blockIdx.x] = incl;
}

__global__ void scanBC_kernel() {
    __shared__ int sb[64];
    if (threadIdx.x < 32) {
        int lane = threadIdx.x;
        int i0 = 2 * lane, i1 = 2 * lane + 1;
        int a = (i0 < SCAN_NB) ? g_bsum[i0] : 0;
        int b = (i1 < SCAN_NB) ? g_bsum[i1] : 0;
        int loc = a + b;
        int x = loc;
#pragma unroll
        for (int o = 1; o < 32; o <<= 1) {
            int t = __shfl_up_sync(0xffffffffu, x, o);
            if (lane >= o) x += t;
        }
        int excl = x - loc;
        sb[i0] = excl;
        sb[i1] = excl + a;
        if (lane == 31 && blockIdx.x == 0) g_start[N_NODES] = x;
    }
    __syncthreads();
    int boff = sb[blockIdx.x];
    int i = blockIdx.x * 1024 + threadIdx.x;
    if (i < N_NODES) g_start[i] += boff;
}

__global__ void scatter_kernel(int ET) {
    int i = blockIdx.x * blockDim.x + threadIdx.x;
    if (i >= ET) return;
    int d = g_dst[i];
    int pos = g_start[d] + atomicAdd(&g_cnt[d], 1);
    g_csr_src[pos] = g_src[i];
}

// ------------------------- GEMM: h1 = x @ W1 (prefetched, fused attdot, fp16 store) -------------------------
#define BM 128
#define BK 8
__global__ void __launch_bounds__(256, 2)
gemm1_kernel(const float* __restrict__ X, const float* __restrict__ W,
             const float* __restrict__ att_s, const float* __restrict__ att_d, int M) {
    __shared__ __align__(16) float As[BK][BM];
    __shared__ __align__(16) float Bs[BK][F1];
    __shared__ float s_as[F1], s_ad[F1];
    int tid = threadIdx.x;
    int tx = tid & 15;
    int ty = tid >> 4;
    int rowBase = blockIdx.x * BM;

    if (tid < F1) { s_as[tid] = att_s[tid]; s_ad[tid] = att_d[tid]; }

    int lrow = tid >> 1;
    int lhalf = tid & 1;
    int grow = rowBase + lrow;
    const float* Xrow = X + (size_t)grow * FIN;
    int wrow = tid >> 5;
    int wcol = (tid & 31) * 4;

    float acc[8][8];
#pragma unroll
    for (int i = 0; i < 8; i++)
#pragma unroll
        for (int j = 0; j < 8; j++) acc[i][j] = 0.f;

    float4 xv = make_float4(0.f, 0.f, 0.f, 0.f);
    if (grow < M) xv = *(const float4*)(Xrow + lhalf * 4);
    float4 wv = *(const float4*)&W[(size_t)wrow * F1 + wcol];

    for (int k0 = 0; k0 < FIN; k0 += BK) {
        As[lhalf * 4 + 0][lrow] = xv.x;
        As[lhalf * 4 + 1][lrow] = xv.y;
        As[lhalf * 4 + 2][lrow] = xv.z;
        As[lhalf * 4 + 3][lrow] = xv.w;
        *(float4*)&Bs[wrow][wcol] = wv;
        __syncthreads();
        if (k0 + BK < FIN) {
            xv = make_float4(0.f, 0.f, 0.f, 0.f);
            if (grow < M) xv = *(const float4*)(Xrow + k0 + BK + lhalf * 4);
            wv = *(const float4*)&W[(size_t)(k0 + BK + wrow) * F1 + wcol];
        }
#pragma unroll
        for (int kk = 0; kk < BK; kk++) {
            float4 a0 = *(const float4*)&As[kk][ty * 8];
            float4 a1 = *(const float4*)&As[kk][ty * 8 + 4];
            float4 b0 = *(const float4*)&Bs[kk][tx * 8];
            float4 b1 = *(const float4*)&Bs[kk][tx * 8 + 4];
            float av[8] = {a0.x, a0.y, a0.z, a0.w, a1.x, a1.y, a1.z, a1.w};
            float bv[8] = {b0.x, b0.y, b0.z, b0.w, b1.x, b1.y, b1.z, b1.w};
#pragma unroll
            for (int i = 0; i < 8; i++)
#pragma unroll
                for (int j = 0; j < 8; j++) acc[i][j] += av[i] * bv[j];
        }
        __syncthreads();
    }

    int head = tx >> 1;
    int cbase = head * 16 + (tx & 1) * 8;
#pragma unroll
    for (int i = 0; i < 8; i++) {
        int gr = rowBase + ty * 8 + i;
        if (gr < M) {
            __half2 h0 = __floats2half2_rn(acc[i][0], acc[i][1]);
            __half2 h1v = __floats2half2_rn(acc[i][2], acc[i][3]);
            __half2 h2v = __floats2half2_rn(acc[i][4], acc[i][5]);
            __half2 h3 = __floats2half2_rn(acc[i][6], acc[i][7]);
            uint4 pk;
            pk.x = *(unsigned*)&h0; pk.y = *(unsigned*)&h1v;
            pk.z = *(unsigned*)&h2v; pk.w = *(unsigned*)&h3;
            *(uint4*)&g_h1h[(size_t)gr * F1 + tx * 8] = pk;
        }
        float ps = 0.f, pd = 0.f;
#pragma unroll
        for (int j = 0; j < 8; j++) {
            ps += acc[i][j] * s_as[cbase + j];
            pd += acc[i][j] * s_ad[cbase + j];
        }
        ps += __shfl_xor_sync(0xffffffffu, ps, 1);
        pd += __shfl_xor_sync(0xffffffffu, pd, 1);
        if ((tx & 1) == 0 && gr < M) {
            g_asrc[gr * H1 + head] = ps;
            g_adst[gr * H1 + head] = pd;
        }
    }
}

// ------------------------- fused layer-1: 2 warps per node, softmax-aggregate + elu + W2 + att2 dots -------------------------
__device__ __forceinline__ void loadH4(int s, int lane, float* f) {
    uint2 u = *(const uint2*)&g_h1h[(size_t)s * F1 + lane * 4];
    float2 p0 = __half22float2(*(__half2*)&u.x);
    float2 p1 = __half22float2(*(__half2*)&u.y);
    f[0] = p0.x; f[1] = p0.y; f[2] = p1.x; f[3] = p1.y;
}

// blockDim 256 = 8 warps = 4 nodes/block (2 warps per node). 50000 = 4 * 12500 (no remainder).
__global__ void __launch_bounds__(256)
node1_kernel(const float* __restrict__ b1, const float* __restrict__ W2,
             const float* __restrict__ as2, const float* __restrict__ ad2) {
    __shared__ __align__(16) float s_acc[4][32][4];   // partials from half==1 warp
    __shared__ float s_sum[4][32];

    int wib = threadIdx.x >> 5;      // 0..7
    int slot = wib >> 1;             // 0..3
    int half = wib & 1;              // 0/1
    int lane = threadIdx.x & 31;
    int n = blockIdx.x * 4 + slot;   // always < N_NODES (grid exact)

    int rs = g_start[n], re = g_start[n + 1];
    int deg = re - rs;
    int mid = rs + ((deg + 1) >> 1);
    int js = half ? mid : rs;
    int je = half ? re : mid;

    int myh = lane >> 2;
    float adm = g_adst[n * H1 + myh];
    float ssum = 0.f;
    float acc0 = 0.f, acc1 = 0.f, acc2 = 0.f, acc3 = 0.f;

    int j = js;
    for (; j + 3 < je; j += 4) {
        int s0 = g_csr_src[j];
        int s1 = g_csr_src[j + 1];
        int s2 = g_csr_src[j + 2];
        int s3 = g_csr_src[j + 3];
        float av0 = __ldg(&g_asrc[s0 * H1 + myh]);
        float av1 = __ldg(&g_asrc[s1 * H1 + myh]);
        float av2 = __ldg(&g_asrc[s2 * H1 + myh]);
        float av3 = __ldg(&g_asrc[s3 * H1 + myh]);
        float f0[4], f1[4], f2[4], f3[4];
        loadH4(s0, lane, f0);
        loadH4(s1, lane, f1);
        loadH4(s2, lane, f2);
        loadH4(s3, lane, f3);
        float ee0 = __expf(leaky(av0 + adm));
        float ee1 = __expf(leaky(av1 + adm));
        float ee2 = __expf(leaky(av2 + adm));
        float ee3 = __expf(leaky(av3 + adm));
        ssum += (ee0 + ee1) + (ee2 + ee3);
        acc0 += ee0 * f0[0] + ee1 * f1[0] + ee2 * f2[0] + ee3 * f3[0];
        acc1 += ee0 * f0[1] + ee1 * f1[1] + ee2 * f2[1] + ee3 * f3[1];
        acc2 += ee0 * f0[2] + ee1 * f1[2] + ee2 * f2[2] + ee3 * f3[2];
        acc3 += ee0 * f0[3] + ee1 * f1[3] + ee2 * f2[3] + ee3 * f3[3];
    }
    for (; j < je; j++) {
        int s0 = g_csr_src[j];
        float av0 = __ldg(&g_asrc[s0 * H1 + myh]);
        float f0[4];
        loadH4(s0, lane, f0);
        float ee0 = __expf(leaky(av0 + adm));
        ssum += ee0;
        acc0 += ee0 * f0[0]; acc1 += ee0 * f0[1]; acc2 += ee0 * f0[2]; acc3 += ee0 * f0[3];
    }

    // combine the two halves
    if (half == 1) {
        *(float4*)&s_acc[slot][lane][0] = make_float4(acc0, acc1, acc2, acc3);
        s_sum[slot][lane] = ssum;
    }
    __syncthreads();
    if (half == 1) return;

    {
        float4 o = *(const float4*)&s_acc[slot][lane][0];
        acc0 += o.x; acc1 += o.y; acc2 += o.z; acc3 += o.w;
        ssum += s_sum[slot][lane];
    }
    float inv = 1.f / ssum;

    float4 bv = *(const float4*)&b1[lane * 4];
    float v0 = acc0 * inv + bv.x;
    float v1 = acc1 * inv + bv.y;
    float v2 = acc2 * inv + bv.z;
    float v3 = acc3 * inv + bv.w;
    v0 = v0 > 0.f ? v0 : expm1f(v0);
    v1 = v1 > 0.f ? v1 : expm1f(v1);
    v2 = v2 > 0.f ? v2 : expm1f(v2);
    v3 = v3 > 0.f ? v3 : expm1f(v3);
    const float4* W4 = (const float4*)W2;
    float4 wa = W4[lane * 2];
    float4 wb = W4[lane * 2 + 1];
    float p0 = v0 * wa.x + v1 * wa.z + v2 * wb.x + v3 * wb.z;
    float p1 = v0 * wa.y + v1 * wa.w + v2 * wb.y + v3 * wb.w;
#pragma unroll
    for (int o = 16; o > 0; o >>= 1) {
        p0 += __shfl_xor_sync(0xffffffffu, p0, o);
        p1 += __shfl_xor_sync(0xffffffffu, p1, o);
    }
    if (lane == 0) {
        float a2s = p0 * as2[0] + p1 * as2[1];
        g_n2[n] = make_float4(a2s, p0, p1, 0.f);
        g_a2d[n] = p0 * ad2[0] + p1 * ad2[1];
    }
}

// ------------------------- fused layer-2: single-pass softmax-aggregate (packed gathers) -------------------------
__global__ void node2_kernel(float* __restrict__ out, const float* __restrict__ b2) {
    int n = (blockIdx.x * blockDim.x + threadIdx.x) >> 5;
    if (n >= N_NODES) return;
    int lane = threadIdx.x & 31;
    int rs = g_start[n], re = g_start[n + 1];
    float a2dn = g_a2d[n];

    float S = 0.f, n0 = 0.f, n1 = 0.f;
    for (int j = rs + lane; j < re; j += 32) {
        int s = g_csr_src[j];
        float4 v = g_n2[s];
        float ee = __expf(leaky(v.x + a2dn));
        S += ee; n0 += ee * v.y; n1 += ee * v.z;
    }
#pragma unroll
    for (int o = 16; o > 0; o >>= 1) {
        S  += __shfl_xor_sync(0xffffffffu, S, o);
        n0 += __shfl_xor_sync(0xffffffffu, n0, o);
        n1 += __shfl_xor_sync(0xffffffffu, n1, o);
    }
    if (lane == 0) {
        float inv = 1.f / S;
        out[n * 2]     = n0 * inv + b2[0];
        out[n * 2 + 1] = n1 * inv + b2[1];
    }
}

// ------------------------- launch (stream fork/join: gemm ∥ CSR build) -------------------------
extern "C" void kernel_launch(void* const* d_in, const int* in_sizes, int n_in,
                              void* d_out, int out_size) {
    const float* x   = (const float*)d_in[0];
    const void*  ei  = d_in[1];
    const float* W1  = (const float*)d_in[2];
    const float* as1 = (const float*)d_in[3];
    const float* ad1 = (const float*)d_in[4];
    const float* b1  = (const float*)d_in[5];
    const float* W2  = (const float*)d_in[6];
    const float* as2 = (const float*)d_in[7];
    const float* ad2 = (const float*)d_in[8];
    const float* b2  = (const float*)d_in[9];
    float* out = (float*)d_out;

    int E  = in_sizes[1] / 2;
    int ET = E + N_NODES;

    cudaStream_t sB;
    cudaEvent_t evFork, evJoin;
    cudaStreamCreateWithFlags(&sB, cudaStreamNonBlocking);
    cudaEventCreateWithFlags(&evFork, cudaEventDisableTiming);
    cudaEventCreateWithFlags(&evJoin, cudaEventDisableTiming);

    // fork gemm onto stream B
    cudaEventRecord(evFork, 0);
    cudaStreamWaitEvent(sB, evFork, 0);
    gemm1_kernel<<<(N_NODES + BM - 1) / BM, 256, 0, sB>>>(x, W1, as1, ad1, N_NODES);
    cudaEventRecord(evJoin, sB);

    // CSR build on default stream
    probe_zero_kernel<<<(N_NODES + 255) / 256, 256>>>(ei);
    convert_kernel<<<(ET + 255) / 256, 256>>>(ei, E, ET);
    scanA_kernel<<<SCAN_NB, 1024>>>();
    scanBC_kernel<<<SCAN_NB, 1024>>>();
    scatter_kernel<<<(ET + 255) / 256, 256>>>(ET);

    cudaStreamWaitEvent(0, evJoin, 0);

    node1_kernel<<<N_NODES / 4, 256>>>(b1, W2, as2, ad2);     // 12500 blocks, 2 warps/node
    node2_kernel<<<(N_NODES * 32 + 255) / 256, 256>>>(out, b2);
}

// round 13
// speedup vs baseline: 1.0443x; 1.0443x over previous
#include <cuda_runtime.h>
#include <cuda_fp16.h>
#include <math.h>

#define N_NODES 50000
#define FIN 128
#define H1 8
#define F1 128
#define E_MAX 800000
#define ET_MAX (E_MAX + N_NODES)
#define NEG_SLOPE 0.2f
#define SCAN_NB ((N_NODES + 1023) / 1024)   // 49

// ------------------------- scratch -------------------------
__device__ __half g_h1h[N_NODES * F1];     // fp16 x @ W1 (node1 gathers)
__device__ float g_asrc[N_NODES * H1];
__device__ float g_adst[N_NODES * H1];
__device__ float4 g_n2[N_NODES];           // packed (a2s, h2.x, h2.y, 0)
__device__ float g_a2d[N_NODES];
__device__ int   g_srcb[ET_MAX];
__device__ int   g_pk[ET_MAX];             // dst | rank<<17
__device__ int   g_csr_src[ET_MAX];
__device__ int   g_start[N_NODES + 1];
__device__ int   g_deg[N_NODES];
__device__ int   g_bsum[SCAN_NB];
__device__ int   g_scan_ready;
__device__ int   g_is64;

__device__ __forceinline__ float leaky(float v) { return v > 0.f ? v : NEG_SLOPE * v; }

// ------------------------- dtype probe + zero (counters + scan flag) -------------------------
__global__ void probe_zero_kernel(const void* ei) {
    int i = blockIdx.x * blockDim.x + threadIdx.x;
    if (i < N_NODES) g_deg[i] = 0;
    if (i == 0) g_scan_ready = 0;
    if (blockIdx.x == 0) {
        const long long* p = (const long long*)ei;
        int bad = 0;
        for (int k = threadIdx.x; k < 2048; k += 256) {
            long long v = p[k];
            if (v < 0 || v >= (long long)N_NODES) bad = 1;
        }
        bad = __syncthreads_or(bad);
        if (threadIdx.x == 0) g_is64 = bad ? 0 : 1;
    }
}

// ------------------------- convert: histogram + per-edge rank -------------------------
__global__ void convert_kernel(const void* ei, int E, int ET) {
    int i = blockIdx.x * blockDim.x + threadIdx.x;
    if (i >= ET) return;
    int s, d;
    if (i < E) {
        if (g_is64) {
            const long long* p = (const long long*)ei;
            s = (int)p[i]; d = (int)p[E + i];
        } else {
            const int* p = (const int*)ei;
            s = p[i]; d = p[E + i];
        }
    } else {
        s = d = i - E;
    }
    int r = atomicAdd(&g_deg[d], 1);
    g_srcb[i] = s;
    g_pk[i] = d | (r << 17);
}

// ------------------------- single-kernel scan (49 co-resident blocks, spin-wait) -------------------------
__global__ void scan_kernel() {
    int i = blockIdx.x * 1024 + threadIdx.x;
    int v = (i < N_NODES) ? g_deg[i] : 0;
    int lane = threadIdx.x & 31, wid = threadIdx.x >> 5;
    int x = v;
#pragma unroll
    for (int o = 1; o < 32; o <<= 1) {
        int t = __shfl_up_sync(0xffffffffu, x, o);
        if (lane >= o) x += t;
    }
    __shared__ int wsum[32];
    __shared__ int sb[64];
    if (lane == 31) wsum[wid] = x;
    __syncthreads();
    if (wid == 0) {
        int y = wsum[lane];
#pragma unroll
        for (int o = 1; o < 32; o <<= 1) {
            int t = __shfl_up_sync(0xffffffffu, y, o);
            if (lane >= o) y += t;
        }
        wsum[lane] = y;
    }
    __syncthreads();
    int incl = x + (wid > 0 ? wsum[wid - 1] : 0);
    int excl_local = incl - v;

    // publish block total
    if (threadIdx.x == 1023) {
        g_bsum[blockIdx.x] = incl;
        __threadfence();
        atomicAdd(&g_scan_ready, 1);
    }
    // warp 0 waits for all blocks, scans the 49 block sums
    if (wid == 0) {
        if (lane == 0) {
            while (*(volatile int*)&g_scan_ready < SCAN_NB) {}
        }
        __syncwarp();
        __threadfence();
        int i0 = 2 * lane, i1 = 2 * lane + 1;
        int a = (i0 < SCAN_NB) ? g_bsum[i0] : 0;
        int b = (i1 < SCAN_NB) ? g_bsum[i1] : 0;
        int loc = a + b;
        int y = loc;
#pragma unroll
        for (int o = 1; o < 32; o <<= 1) {
            int t = __shfl_up_sync(0xffffffffu, y, o);
            if (lane >= o) y += t;
        }
        int excl = y - loc;
        sb[i0] = excl;
        sb[i1] = excl + a;
        if (lane == 31 && blockIdx.x == 0) g_start[N_NODES] = y;   // grand total
    }
    __syncthreads();
    if (i < N_NODES) g_start[i] = excl_local + sb[blockIdx.x];
}

// ------------------------- scatter (atomic-free: rank precomputed) -------------------------
__global__ void scatter_kernel(int ET) {
    int i = blockIdx.x * blockDim.x + threadIdx.x;
    if (i >= ET) return;
    int pk = g_pk[i];
    int d = pk & 131071;
    int r = pk >> 17;
    g_csr_src[g_start[d] + r] = g_srcb[i];
}

// ------------------------- GEMM: h1 = x @ W1 (prefetched, fused attdot, fp16 store) -------------------------
#define BM 128
#define BK 8
__global__ void __launch_bounds__(256, 2)
gemm1_kernel(const float* __restrict__ X, const float* __restrict__ W,
             const float* __restrict__ att_s, const float* __restrict__ att_d, int M) {
    __shared__ __align__(16) float As[BK][BM];
    __shared__ __align__(16) float Bs[BK][F1];
    __shared__ float s_as[F1], s_ad[F1];
    int tid = threadIdx.x;
    int tx = tid & 15;
    int ty = tid >> 4;
    int rowBase = blockIdx.x * BM;

    if (tid < F1) { s_as[tid] = att_s[tid]; s_ad[tid] = att_d[tid]; }

    int lrow = tid >> 1;
    int lhalf = tid & 1;
    int grow = rowBase + lrow;
    const float* Xrow = X + (size_t)grow * FIN;
    int wrow = tid >> 5;
    int wcol = (tid & 31) * 4;

    float acc[8][8];
#pragma unroll
    for (int i = 0; i < 8; i++)
#pragma unroll
        for (int j = 0; j < 8; j++) acc[i][j] = 0.f;

    float4 xv = make_float4(0.f, 0.f, 0.f, 0.f);
    if (grow < M) xv = *(const float4*)(Xrow + lhalf * 4);
    float4 wv = *(const float4*)&W[(size_t)wrow * F1 + wcol];

    for (int k0 = 0; k0 < FIN; k0 += BK) {
        As[lhalf * 4 + 0][lrow] = xv.x;
        As[lhalf * 4 + 1][lrow] = xv.y;
        As[lhalf * 4 + 2][lrow] = xv.z;
        As[lhalf * 4 + 3][lrow] = xv.w;
        *(float4*)&Bs[wrow][wcol] = wv;
        __syncthreads();
        if (k0 + BK < FIN) {
            xv = make_float4(0.f, 0.f, 0.f, 0.f);
            if (grow < M) xv = *(const float4*)(Xrow + k0 + BK + lhalf * 4);
            wv = *(const float4*)&W[(size_t)(k0 + BK + wrow) * F1 + wcol];
        }
#pragma unroll
        for (int kk = 0; kk < BK; kk++) {
            float4 a0 = *(const float4*)&As[kk][ty * 8];
            float4 a1 = *(const float4*)&As[kk][ty * 8 + 4];
            float4 b0 = *(const float4*)&Bs[kk][tx * 8];
            float4 b1 = *(const float4*)&Bs[kk][tx * 8 + 4];
            float av[8] = {a0.x, a0.y, a0.z, a0.w, a1.x, a1.y, a1.z, a1.w};
            float bv[8] = {b0.x, b0.y, b0.z, b0.w, b1.x, b1.y, b1.z, b1.w};
#pragma unroll
            for (int i = 0; i < 8; i++)
#pragma unroll
                for (int j = 0; j < 8; j++) acc[i][j] += av[i] * bv[j];
        }
        __syncthreads();
    }

    int head = tx >> 1;
    int cbase = head * 16 + (tx & 1) * 8;
#pragma unroll
    for (int i = 0; i < 8; i++) {
        int gr = rowBase + ty * 8 + i;
        if (gr < M) {
            __half2 h0 = __floats2half2_rn(acc[i][0], acc[i][1]);
            __half2 h1v = __floats2half2_rn(acc[i][2], acc[i][3]);
            __half2 h2v = __floats2half2_rn(acc[i][4], acc[i][5]);
            __half2 h3 = __floats2half2_rn(acc[i][6], acc[i][7]);
            uint4 pk;
            pk.x = *(unsigned*)&h0; pk.y = *(unsigned*)&h1v;
            pk.z = *(unsigned*)&h2v; pk.w = *(unsigned*)&h3;
            *(uint4*)&g_h1h[(size_t)gr * F1 + tx * 8] = pk;
        }
        float ps = 0.f, pd = 0.f;
#pragma unroll
        for (int j = 0; j < 8; j++) {
            ps += acc[i][j] * s_as[cbase + j];
            pd += acc[i][j] * s_ad[cbase + j];
        }
        ps += __shfl_xor_sync(0xffffffffu, ps, 1);
        pd += __shfl_xor_sync(0xffffffffu, pd, 1);
        if ((tx & 1) == 0 && gr < M) {
            g_asrc[gr * H1 + head] = ps;
            g_adst[gr * H1 + head] = pd;
        }
    }
}

// ------------------------- fused layer-1: single-pass softmax-aggregate + elu + W2 + att2 dots -------------------------
__device__ __forceinline__ void loadH4(int s, int lane, float* f) {
    uint2 u = *(const uint2*)&g_h1h[(size_t)s * F1 + lane * 4];
    float2 p0 = __half22float2(*(__half2*)&u.x);
    float2 p1 = __half22float2(*(__half2*)&u.y);
    f[0] = p0.x; f[1] = p0.y; f[2] = p1.x; f[3] = p1.y;
}

__global__ void node1_kernel(const float* __restrict__ b1, const float* __restrict__ W2,
                             const float* __restrict__ as2, const float* __restrict__ ad2) {
    int n = (blockIdx.x * blockDim.x + threadIdx.x) >> 5;
    if (n >= N_NODES) return;
    int lane = threadIdx.x & 31;
    int rs = g_start[n], re = g_start[n + 1];

    int myh = lane >> 2;
    float adm = g_adst[n * H1 + myh];
    float ssum = 0.f;
    float acc0 = 0.f, acc1 = 0.f, acc2 = 0.f, acc3 = 0.f;

    int j = rs;
    for (; j + 3 < re; j += 4) {
        int s0 = g_csr_src[j];
        int s1 = g_csr_src[j + 1];
        int s2 = g_csr_src[j + 2];
        int s3 = g_csr_src[j + 3];
        float av0 = __ldg(&g_asrc[s0 * H1 + myh]);
        float av1 = __ldg(&g_asrc[s1 * H1 + myh]);
        float av2 = __ldg(&g_asrc[s2 * H1 + myh]);
        float av3 = __ldg(&g_asrc[s3 * H1 + myh]);
        float f0[4], f1[4], f2[4], f3[4];
        loadH4(s0, lane, f0);
        loadH4(s1, lane, f1);
        loadH4(s2, lane, f2);
        loadH4(s3, lane, f3);
        float ee0 = __expf(leaky(av0 + adm));
        float ee1 = __expf(leaky(av1 + adm));
        float ee2 = __expf(leaky(av2 + adm));
        float ee3 = __expf(leaky(av3 + adm));
        ssum += (ee0 + ee1) + (ee2 + ee3);
        acc0 += ee0 * f0[0] + ee1 * f1[0] + ee2 * f2[0] + ee3 * f3[0];
        acc1 += ee0 * f0[1] + ee1 * f1[1] + ee2 * f2[1] + ee3 * f3[1];
        acc2 += ee0 * f0[2] + ee1 * f1[2] + ee2 * f2[2] + ee3 * f3[2];
        acc3 += ee0 * f0[3] + ee1 * f1[3] + ee2 * f2[3] + ee3 * f3[3];
    }
    for (; j < re; j++) {
        int s0 = g_csr_src[j];
        float av0 = __ldg(&g_asrc[s0 * H1 + myh]);
        float f0[4];
        loadH4(s0, lane, f0);
        float ee0 = __expf(leaky(av0 + adm));
        ssum += ee0;
        acc0 += ee0 * f0[0]; acc1 += ee0 * f0[1]; acc2 += ee0 * f0[2]; acc3 += ee0 * f0[3];
    }
    float inv = 1.f / ssum;

    float4 bv = *(const float4*)&b1[lane * 4];
    float v0 = acc0 * inv + bv.x;
    float v1 = acc1 * inv + bv.y;
    float v2 = acc2 * inv + bv.z;
    float v3 = acc3 * inv + bv.w;
    v0 = v0 > 0.f ? v0 : expm1f(v0);
    v1 = v1 > 0.f ? v1 : expm1f(v1);
    v2 = v2 > 0.f ? v2 : expm1f(v2);
    v3 = v3 > 0.f ? v3 : expm1f(v3);
    const float4* W4 = (const float4*)W2;
    float4 wa = W4[lane * 2];
    float4 wb = W4[lane * 2 + 1];
    float p0 = v0 * wa.x + v1 * wa.z + v2 * wb.x + v3 * wb.z;
    float p1 = v0 * wa.y + v1 * wa.w + v2 * wb.y + v3 * wb.w;
#pragma unroll
    for (int o = 16; o > 0; o >>= 1) {
        p0 += __shfl_xor_sync(0xffffffffu, p0, o);
        p1 += __shfl_xor_sync(0xffffffffu, p1, o);
    }
    if (lane == 0) {
        float a2s = p0 * as2[0] + p1 * as2[1];
        g_n2[n] = make_float4(a2s, p0, p1, 0.f);
        g_a2d[n] = p0 * ad2[0] + p1 * ad2[1];
    }
}

// ------------------------- fused layer-2: single-pass softmax-aggregate (packed gathers) -------------------------
__global__ void node2_kernel(float* __restrict__ out, const float* __restrict__ b2) {
    int n = (blockIdx.x * blockDim.x + threadIdx.x) >> 5;
    if (n >= N_NODES) return;
    int lane = threadIdx.x & 31;
    int rs = g_start[n], re = g_start[n + 1];
    float a2dn = g_a2d[n];

    float S = 0.f, n0 = 0.f, n1 = 0.f;
    for (int j = rs + lane; j < re; j += 32) {
        int s = g_csr_src[j];
        float4 v = g_n2[s];
        float ee = __expf(leaky(v.x + a2dn));
        S += ee; n0 += ee * v.y; n1 += ee * v.z;
    }
#pragma unroll
    for (int o = 16; o > 0; o >>= 1) {
        S  += __shfl_xor_sync(0xffffffffu, S, o);
        n0 += __shfl_xor_sync(0xffffffffu, n0, o);
        n1 += __shfl_xor_sync(0xffffffffu, n1, o);
    }
    if (lane == 0) {
        float inv = 1.f / S;
        out[n * 2]     = n0 * inv + b2[0];
        out[n * 2 + 1] = n1 * inv + b2[1];
    }
}

// ------------------------- launch (stream fork/join: gemm ∥ CSR build) -------------------------
extern "C" void kernel_launch(void* const* d_in, const int* in_sizes, int n_in,
                              void* d_out, int out_size) {
    const float* x   = (const float*)d_in[0];
    const void*  ei  = d_in[1];
    const float* W1  = (const float*)d_in[2];
    const float* as1 = (const float*)d_in[3];
    const float* ad1 = (const float*)d_in[4];
    const float* b1  = (const float*)d_in[5];
    const float* W2  = (const float*)d_in[6];
    const float* as2 = (const float*)d_in[7];
    const float* ad2 = (const float*)d_in[8];
    const float* b2  = (const float*)d_in[9];
    float* out = (float*)d_out;

    int E  = in_sizes[1] / 2;
    int ET = E + N_NODES;

    cudaStream_t sB;
    cudaEvent_t evFork, evJoin;
    cudaStreamCreateWithFlags(&sB, cudaStreamNonBlocking);
    cudaEventCreateWithFlags(&evFork, cudaEventDisableTiming);
    cudaEventCreateWithFlags(&evJoin, cudaEventDisableTiming);

    // fork gemm onto stream B
    cudaEventRecord(evFork, 0);
    cudaStreamWaitEvent(sB, evFork, 0);
    gemm1_kernel<<<(N_NODES + BM - 1) / BM, 256, 0, sB>>>(x, W1, as1, ad1, N_NODES);
    cudaEventRecord(evJoin, sB);

    // CSR build on default stream
    probe_zero_kernel<<<(N_NODES + 255) / 256, 256>>>(ei);
    convert_kernel<<<(ET + 255) / 256, 256>>>(ei, E, ET);
    scan_kernel<<<SCAN_NB, 1024>>>();
    scatter_kernel<<<(ET + 255) / 256, 256>>>(ET);

    cudaStreamWaitEvent(0, evJoin, 0);

    node1_kernel<<<(N_NODES * 32 + 255) / 256, 256>>>(b1, W2, as2, ad2);
    node2_kernel<<<(N_NODES * 32 + 255) / 256, 256>>>(out, b2);
}